// round 1
// baseline (speedup 1.0000x reference)
#include <cuda_runtime.h>

#define B_   4
#define S_   2048
#define DIN  1024
#define DM   1024
#define H_   16
#define HD_  64

// Scratch for projected q/k/v in [B][H][S][HD] layout (static device arrays: no allocs)
__device__ float g_q[B_ * H_ * S_ * HD_];
__device__ float g_k[B_ * H_ * S_ * HD_];
__device__ float g_v[B_ * H_ * S_ * HD_];

// ---------------------------------------------------------------------------
// Projection GEMM: out[b][h][s][hd] = X[row] @ W[:, col] + bias[col]
// M=8192 (=B*S), N=1024, K=1024. 128x128 tile, BK=8, 256 threads, 8x8 micro.
// ---------------------------------------------------------------------------
__global__ __launch_bounds__(256)
void proj_kernel(const float* __restrict__ X,
                 const float* __restrict__ W,
                 const float* __restrict__ bias,
                 int which)
{
    __shared__ float As[8][128];
    __shared__ float Bs[8][128];

    float* out = (which == 0) ? g_q : (which == 1) ? g_k : g_v;

    const int tid = threadIdx.x;
    const int tx  = tid & 15;
    const int ty  = tid >> 4;
    const int row0 = blockIdx.y * 128;
    const int col0 = blockIdx.x * 128;

    const int a_row = tid >> 1;            // 0..127
    const int a_col = (tid & 1) << 2;      // 0 or 4
    const int b_row = tid >> 5;            // 0..7
    const int b_col = (tid & 31) << 2;     // 0..124

    float acc[8][8];
#pragma unroll
    for (int i = 0; i < 8; ++i)
#pragma unroll
        for (int j = 0; j < 8; ++j) acc[i][j] = 0.f;

    const float* Xp = X + (size_t)(row0 + a_row) * DIN + a_col;
    const float* Wp = W + (size_t)b_row * DM + col0 + b_col;

    for (int k0 = 0; k0 < DIN; k0 += 8) {
        float4 av = *(const float4*)(Xp + k0);
        float4 bv = *(const float4*)(Wp + (size_t)k0 * DM);
        __syncthreads();
        As[a_col + 0][a_row] = av.x;
        As[a_col + 1][a_row] = av.y;
        As[a_col + 2][a_row] = av.z;
        As[a_col + 3][a_row] = av.w;
        *(float4*)&Bs[b_row][b_col] = bv;
        __syncthreads();
#pragma unroll
        for (int kk = 0; kk < 8; ++kk) {
            float a[8], b[8];
            *(float4*)(a)     = *(const float4*)&As[kk][ty * 8];
            *(float4*)(a + 4) = *(const float4*)&As[kk][ty * 8 + 4];
            *(float4*)(b)     = *(const float4*)&Bs[kk][tx * 8];
            *(float4*)(b + 4) = *(const float4*)&Bs[kk][tx * 8 + 4];
#pragma unroll
            for (int i = 0; i < 8; ++i)
#pragma unroll
                for (int j = 0; j < 8; ++j)
                    acc[i][j] = fmaf(a[i], b[j], acc[i][j]);
        }
    }

    // Epilogue: add bias, scatter into [b][h][s][hd] layout.
    float bb[8];
    *(float4*)(bb)     = *(const float4*)(bias + col0 + tx * 8);
    *(float4*)(bb + 4) = *(const float4*)(bias + col0 + tx * 8 + 4);

    const int col = col0 + tx * 8;
    const int h   = col >> 6;   // head
    const int hd  = col & 63;   // within head (tx*8 multiple of 8 -> stays in head)
#pragma unroll
    for (int i = 0; i < 8; ++i) {
        int row = row0 + ty * 8 + i;
        int bat = row >> 11;    // /2048
        int s   = row & 2047;
        float* dst = out + ((size_t)((bat * H_ + h) * S_ + s)) * HD_ + hd;
        float4 v0, v1;
        v0.x = acc[i][0] + bb[0]; v0.y = acc[i][1] + bb[1];
        v0.z = acc[i][2] + bb[2]; v0.w = acc[i][3] + bb[3];
        v1.x = acc[i][4] + bb[4]; v1.y = acc[i][5] + bb[5];
        v1.z = acc[i][6] + bb[6]; v1.w = acc[i][7] + bb[7];
        *(float4*)dst       = v0;
        *(float4*)(dst + 4) = v1;
    }
}

// ---------------------------------------------------------------------------
// Flash attention, fp32. BR=128 q-rows, BC=64 keys, 256 threads (16x16),
// each thread owns 8 rows x 4 key/hd cols. Online softmax, O = softmax(QK^T)V.
// ---------------------------------------------------------------------------
#define SMEM_FLOATS (64 * 128 + 64 * 65 + 64 * 64 + 64 * 129)

__device__ __forceinline__ float grp_max16(float v) {
    v = fmaxf(v, __shfl_xor_sync(0xffffffffu, v, 1));
    v = fmaxf(v, __shfl_xor_sync(0xffffffffu, v, 2));
    v = fmaxf(v, __shfl_xor_sync(0xffffffffu, v, 4));
    v = fmaxf(v, __shfl_xor_sync(0xffffffffu, v, 8));
    return v;
}
__device__ __forceinline__ float grp_sum16(float v) {
    v += __shfl_xor_sync(0xffffffffu, v, 1);
    v += __shfl_xor_sync(0xffffffffu, v, 2);
    v += __shfl_xor_sync(0xffffffffu, v, 4);
    v += __shfl_xor_sync(0xffffffffu, v, 8);
    return v;
}

__global__ __launch_bounds__(256)
void attn_kernel(float* __restrict__ out)
{
    extern __shared__ float sm[];
    float* Qt = sm;                 // [64 hd][128 rows], stride 128 (float4 bcast reads)
    float* Kt = Qt + 64 * 128;      // [64 hd][64 keys],  stride 65  (scalar, 2-way max)
    float* Vs = Kt + 64 * 65;       // [64 keys][64 hd],  stride 64  (float4 reads)
    float* Pt = Vs + 64 * 64;       // [64 keys][128 rows], stride 129 (scalar bcast reads)

    const int tid = threadIdx.x;
    const int tx  = tid & 15;       // key/hd column group
    const int ty  = tid >> 4;       // row group
    const int bh  = blockIdx.y;     // b*16 + h
    const int q0  = blockIdx.x * 128;

    const float* qp = g_q + (size_t)bh * S_ * HD_;
    const float* kp = g_k + (size_t)bh * S_ * HD_;
    const float* vp = g_v + (size_t)bh * S_ * HD_;

    // Load Q tile [128][64], transposed into Qt[hd][row], pre-scaled by 1/sqrt(64)
#pragma unroll
    for (int m = 0; m < 8; ++m) {
        int idx = m * 256 + tid;            // 0..2047 float4s
        int r   = idx >> 4;                 // 0..127
        int c   = (idx & 15) << 2;          // 0..60
        float4 val = *(const float4*)(qp + (size_t)(q0 + r) * HD_ + c);
        Qt[(c + 0) * 128 + r] = val.x * 0.125f;
        Qt[(c + 1) * 128 + r] = val.y * 0.125f;
        Qt[(c + 2) * 128 + r] = val.z * 0.125f;
        Qt[(c + 3) * 128 + r] = val.w * 0.125f;
    }

    float m_i[8], l_i[8], O[8][4];
#pragma unroll
    for (int i = 0; i < 8; ++i) {
        m_i[i] = -1e30f; l_i[i] = 0.f;
        O[i][0] = O[i][1] = O[i][2] = O[i][3] = 0.f;
    }

    for (int kt = 0; kt < S_ / 64; ++kt) {
        __syncthreads();   // prior PV reads of Pt/Vs (and Kt) done before overwrite
        const int kb = kt * 64;
#pragma unroll
        for (int m = 0; m < 4; ++m) {
            int idx = m * 256 + tid;        // 0..1023 float4s
            int key = idx >> 4;             // 0..63
            int c   = (idx & 15) << 2;      // 0..60
            float4 kv = *(const float4*)(kp + (size_t)(kb + key) * HD_ + c);
            Kt[(c + 0) * 65 + key] = kv.x;
            Kt[(c + 1) * 65 + key] = kv.y;
            Kt[(c + 2) * 65 + key] = kv.z;
            Kt[(c + 3) * 65 + key] = kv.w;
            float4 vv = *(const float4*)(vp + (size_t)(kb + key) * HD_ + c);
            *(float4*)&Vs[key * 64 + c] = vv;
        }
        __syncthreads();

        // S = (Q/sqrt(d)) @ K^T  -- 8x4 per thread
        float sc[8][4];
#pragma unroll
        for (int i = 0; i < 8; ++i)
            sc[i][0] = sc[i][1] = sc[i][2] = sc[i][3] = 0.f;

#pragma unroll 4
        for (int kk = 0; kk < 64; ++kk) {
            float a[8], b[4];
            *(float4*)(a)     = *(const float4*)&Qt[kk * 128 + ty * 8];
            *(float4*)(a + 4) = *(const float4*)&Qt[kk * 128 + ty * 8 + 4];
            b[0] = Kt[kk * 65 + tx * 4 + 0];
            b[1] = Kt[kk * 65 + tx * 4 + 1];
            b[2] = Kt[kk * 65 + tx * 4 + 2];
            b[3] = Kt[kk * 65 + tx * 4 + 3];
#pragma unroll
            for (int i = 0; i < 8; ++i)
#pragma unroll
                for (int j = 0; j < 4; ++j)
                    sc[i][j] = fmaf(a[i], b[j], sc[i][j]);
        }

        // Online softmax update (row reductions across the 16 tx lanes)
#pragma unroll
        for (int i = 0; i < 8; ++i) {
            float mx = fmaxf(fmaxf(sc[i][0], sc[i][1]), fmaxf(sc[i][2], sc[i][3]));
            mx = grp_max16(mx);
            float mnew = fmaxf(m_i[i], mx);
            float corr = __expf(m_i[i] - mnew);
            float rs = 0.f;
#pragma unroll
            for (int j = 0; j < 4; ++j) {
                float p = __expf(sc[i][j] - mnew);
                sc[i][j] = p;
                rs += p;
            }
            rs = grp_sum16(rs);
            l_i[i] = l_i[i] * corr + rs;
            m_i[i] = mnew;
            O[i][0] *= corr; O[i][1] *= corr; O[i][2] *= corr; O[i][3] *= corr;
        }

        // Store P transposed: Pt[key][row]
#pragma unroll
        for (int j = 0; j < 4; ++j)
#pragma unroll
            for (int i = 0; i < 8; ++i)
                Pt[(tx * 4 + j) * 129 + ty * 8 + i] = sc[i][j];
        __syncthreads();

        // O += P @ V
#pragma unroll 4
        for (int kk = 0; kk < 64; ++kk) {
            float a[8], b[4];
            *(float4*)b = *(const float4*)&Vs[kk * 64 + tx * 4];
#pragma unroll
            for (int i = 0; i < 8; ++i) a[i] = Pt[kk * 129 + ty * 8 + i];
#pragma unroll
            for (int i = 0; i < 8; ++i)
#pragma unroll
                for (int j = 0; j < 4; ++j)
                    O[i][j] = fmaf(a[i], b[j], O[i][j]);
        }
    }

    // Epilogue: normalize and write out[b][s][h*64+hd]
    const int bat = bh >> 4;
    const int h   = bh & 15;
#pragma unroll
    for (int i = 0; i < 8; ++i) {
        int s = q0 + ty * 8 + i;
        float inv = 1.0f / l_i[i];
        float4 o;
        o.x = O[i][0] * inv; o.y = O[i][1] * inv;
        o.z = O[i][2] * inv; o.w = O[i][3] * inv;
        *(float4*)(out + (size_t)(bat * S_ + s) * DM + h * HD_ + tx * 4) = o;
    }
}

// ---------------------------------------------------------------------------
extern "C" void kernel_launch(void* const* d_in, const int* in_sizes, int n_in,
                              void* d_out, int out_size)
{
    (void)in_sizes; (void)n_in; (void)out_size;
    // Input order matches reference signature: Q, V, K, wq, bq, wk, bk, wv, bv
    const float* Q  = (const float*)d_in[0];
    const float* V  = (const float*)d_in[1];
    const float* K  = (const float*)d_in[2];
    const float* wq = (const float*)d_in[3];
    const float* bq = (const float*)d_in[4];
    const float* wk = (const float*)d_in[5];
    const float* bk = (const float*)d_in[6];
    const float* wv = (const float*)d_in[7];
    const float* bv = (const float*)d_in[8];
    float* out = (float*)d_out;

    dim3 pg(DM / 128, (B_ * S_) / 128);   // (8, 64)
    proj_kernel<<<pg, 256>>>(Q, wq, bq, 0);
    proj_kernel<<<pg, 256>>>(K, wk, bk, 1);
    proj_kernel<<<pg, 256>>>(V, wv, bv, 2);

    int smem = SMEM_FLOATS * (int)sizeof(float);   // 98816 bytes
    cudaFuncSetAttribute(attn_kernel, cudaFuncAttributeMaxDynamicSharedMemorySize, smem);
    dim3 ag(S_ / 128, B_ * H_);           // (16, 64)
    attn_kernel<<<ag, 256, smem>>>(out);
}

// round 3
// speedup vs baseline: 1.2869x; 1.2869x over previous
#include <cuda_runtime.h>
#include <cuda_bf16.h>
#include <cstdint>

#define B_   4
#define S_   2048
#define DIN  1024
#define DM   1024
#define H_   16
#define HD_  64
#define MX   (B_ * S_)   // 8192

// ---------------- scratch (static device arrays: no allocs) ----------------
__device__ float g_q[(size_t)B_ * H_ * S_ * HD_];
__device__ float g_k[(size_t)B_ * H_ * S_ * HD_];
__device__ float g_v[(size_t)B_ * H_ * S_ * HD_];

// bf16-split operands. X kept [M][K] K-major; W transposed to [N][K] K-major.
__device__ __nv_bfloat16 g_xhi[3][(size_t)MX * DIN];
__device__ __nv_bfloat16 g_xlo[3][(size_t)MX * DIN];
__device__ __nv_bfloat16 g_whi[3][(size_t)DM * DIN];
__device__ __nv_bfloat16 g_wlo[3][(size_t)DM * DIN];

// ---------------- PTX helpers (baseline ISA only: sm_80-class) -------------
__device__ __forceinline__ uint32_t smem_u32(const void* p) {
    uint32_t a;
    asm("{ .reg .u64 t; cvta.to.shared.u64 t, %1; cvt.u32.u64 %0, t; }"
        : "=r"(a) : "l"(p));
    return a;
}

#define CP16(dst, src) \
    asm volatile("cp.async.cg.shared.global [%0], [%1], 16;" \
                 :: "r"(dst), "l"(src) : "memory")
#define CP_COMMIT() asm volatile("cp.async.commit_group;" ::: "memory")
#define CP_WAIT1()  asm volatile("cp.async.wait_group 1;" ::: "memory")
#define CP_WAIT0()  asm volatile("cp.async.wait_group 0;" ::: "memory")

#define LDSM_X4(r0, r1, r2, r3, a) \
    asm volatile("ldmatrix.sync.aligned.m8n8.x4.shared.b16 {%0,%1,%2,%3}, [%4];" \
                 : "=r"(r0), "=r"(r1), "=r"(r2), "=r"(r3) : "r"(a))
#define LDSM_X2(r0, r1, a) \
    asm volatile("ldmatrix.sync.aligned.m8n8.x2.shared.b16 {%0,%1}, [%2];" \
                 : "=r"(r0), "=r"(r1) : "r"(a))

#define MMA_BF16(c, a, b) \
    asm volatile("mma.sync.aligned.m16n8k16.row.col.f32.bf16.bf16.f32 " \
                 "{%0,%1,%2,%3}, {%4,%5,%6,%7}, {%8,%9}, {%0,%1,%2,%3};" \
                 : "+f"((c)[0]), "+f"((c)[1]), "+f"((c)[2]), "+f"((c)[3]) \
                 : "r"((a)[0]), "r"((a)[1]), "r"((a)[2]), "r"((a)[3]), \
                   "r"((b)[0]), "r"((b)[1]))

// ---------------------------------------------------------------------------
// fp32 -> bf16 hi/lo split for X inputs (layout preserved [M][K])
// ---------------------------------------------------------------------------
__global__ __launch_bounds__(256)
void conv_x_kernel(const float* __restrict__ X, int slot)
{
    size_t i = (size_t)blockIdx.x * 256 + threadIdx.x;   // float4 index
    float4 v = ((const float4*)X)[i];
    __nv_bfloat16 h0 = __float2bfloat16(v.x), h1 = __float2bfloat16(v.y);
    __nv_bfloat16 h2 = __float2bfloat16(v.z), h3 = __float2bfloat16(v.w);
    __nv_bfloat16 l0 = __float2bfloat16(v.x - __bfloat162float(h0));
    __nv_bfloat16 l1 = __float2bfloat16(v.y - __bfloat162float(h1));
    __nv_bfloat16 l2 = __float2bfloat16(v.z - __bfloat162float(h2));
    __nv_bfloat16 l3 = __float2bfloat16(v.w - __bfloat162float(h3));
    __nv_bfloat162* hp = reinterpret_cast<__nv_bfloat162*>(g_xhi[slot] + i * 4);
    __nv_bfloat162* lp = reinterpret_cast<__nv_bfloat162*>(g_xlo[slot] + i * 4);
    __nv_bfloat162 a; a.x = h0; a.y = h1; hp[0] = a;
    __nv_bfloat162 b; b.x = h2; b.y = h3; hp[1] = b;
    __nv_bfloat162 c; c.x = l0; c.y = l1; lp[0] = c;
    __nv_bfloat162 d; d.x = l2; d.y = l3; lp[1] = d;
}

// ---------------------------------------------------------------------------
// W [K][N] fp32 -> transposed [N][K] bf16 hi/lo (smem tile transpose)
// ---------------------------------------------------------------------------
__global__ __launch_bounds__(256)
void conv_w_kernel(const float* __restrict__ W, int slot)
{
    __shared__ float t[32][33];
    const int n0 = blockIdx.x * 32, k0 = blockIdx.y * 32;
    const int tx = threadIdx.x & 31, ty = threadIdx.x >> 5;   // ty 0..7
#pragma unroll
    for (int r = 0; r < 32; r += 8)
        t[ty + r][tx] = W[(size_t)(k0 + ty + r) * DM + n0 + tx];
    __syncthreads();
#pragma unroll
    for (int r = 0; r < 32; r += 8) {
        int n = ty + r;
        float x = t[tx][n];                 // W[k0+tx][n0+n]
        __nv_bfloat16 h = __float2bfloat16(x);
        float l = x - __bfloat162float(h);
        size_t o = (size_t)(n0 + n) * DIN + k0 + tx;
        g_whi[slot][o] = h;
        g_wlo[slot][o] = __float2bfloat16(l);
    }
}

// ---------------------------------------------------------------------------
// HMMA projection GEMM: 128x128 CTA tile, 8 warps x (64x32), K-chunk 32,
// double-buffered cp.async, bf16 hi/lo split (3 mma terms), fp32 accum.
// Smem per matrix tile: 128 rows x 32 bf16 padded to 40 (80B rows).
// ---------------------------------------------------------------------------
#define PROJ_TILE_B   10240            // 128 * 40 * 2 bytes
#define PROJ_BUF_B    (4 * PROJ_TILE_B)  // Ah, Al, Bh, Bl
#define PROJ_SMEM     (2 * PROJ_BUF_B)   // double buffer = 81920 B

__global__ __launch_bounds__(256)
void proj_mma_kernel(const float* __restrict__ bias, int which)
{
    extern __shared__ char dsm[];
    const uint32_t sbase = smem_u32(dsm);

    const __nv_bfloat16* Ah = g_xhi[which];
    const __nv_bfloat16* Al = g_xlo[which];
    const __nv_bfloat16* Bh = g_whi[which];
    const __nv_bfloat16* Bl = g_wlo[which];
    float* out = (which == 0) ? g_q : (which == 1) ? g_k : g_v;

    const int tid  = threadIdx.x;
    const int wid  = tid >> 5, lane = tid & 31;
    const int wm   = wid & 1;          // 0..1  (64-row halves)
    const int wn   = wid >> 1;         // 0..3  (32-col quarters)
    const int row0 = blockIdx.y * 128, col0 = blockIdx.x * 128;

    // loader mapping: 2 threads per 64B row-chunk
    const int lrow  = tid >> 1;        // 0..127
    const int lhalf = tid & 1;         // 0/1 -> 32B halves
    const uint32_t sdst = (uint32_t)(lrow * 80 + lhalf * 32);
    const char* gA_h = (const char*)(Ah + (size_t)(row0 + lrow) * DIN) + lhalf * 32;
    const char* gA_l = (const char*)(Al + (size_t)(row0 + lrow) * DIN) + lhalf * 32;
    const char* gB_h = (const char*)(Bh + (size_t)(col0 + lrow) * DIN) + lhalf * 32;
    const char* gB_l = (const char*)(Bl + (size_t)(col0 + lrow) * DIN) + lhalf * 32;

    // ldmatrix per-lane address components
    const int r8 = lane & 7;
    const int ami = lane >> 3;                           // 0..3
    const uint32_t a_off = (uint32_t)(((wm * 64 + (ami & 1) * 8 + r8) * 40
                                       + (ami >> 1) * 8) * 2);
    const int bmi = (lane >> 3) & 1;
    const uint32_t b_off = (uint32_t)(((wn * 32 + r8) * 40 + bmi * 8) * 2);

    float acc[4][4][4];
#pragma unroll
    for (int i = 0; i < 4; ++i)
#pragma unroll
        for (int j = 0; j < 4; ++j) {
            acc[i][j][0] = acc[i][j][1] = acc[i][j][2] = acc[i][j][3] = 0.f;
        }

    // prefetch chunk 0 into buffer 0
    {
        uint32_t b0 = sbase;
        CP16(b0 + sdst,                    gA_h);
        CP16(b0 + sdst + 16,               gA_h + 16);
        CP16(b0 + PROJ_TILE_B + sdst,      gA_l);
        CP16(b0 + PROJ_TILE_B + sdst + 16, gA_l + 16);
        CP16(b0 + 2 * PROJ_TILE_B + sdst,      gB_h);
        CP16(b0 + 2 * PROJ_TILE_B + sdst + 16, gB_h + 16);
        CP16(b0 + 3 * PROJ_TILE_B + sdst,      gB_l);
        CP16(b0 + 3 * PROJ_TILE_B + sdst + 16, gB_l + 16);
        CP_COMMIT();
    }

    for (int c = 0; c < 32; ++c) {
        const uint32_t bufb = sbase + (uint32_t)(c & 1) * PROJ_BUF_B;
        if (c + 1 < 32) {
            const uint32_t nb = sbase + (uint32_t)((c + 1) & 1) * PROJ_BUF_B;
            const int kb = (c + 1) * 64;   // byte offset along K (32 bf16)
            CP16(nb + sdst,                    gA_h + kb);
            CP16(nb + sdst + 16,               gA_h + kb + 16);
            CP16(nb + PROJ_TILE_B + sdst,      gA_l + kb);
            CP16(nb + PROJ_TILE_B + sdst + 16, gA_l + kb + 16);
            CP16(nb + 2 * PROJ_TILE_B + sdst,      gB_h + kb);
            CP16(nb + 2 * PROJ_TILE_B + sdst + 16, gB_h + kb + 16);
            CP16(nb + 3 * PROJ_TILE_B + sdst,      gB_l + kb);
            CP16(nb + 3 * PROJ_TILE_B + sdst + 16, gB_l + kb + 16);
            CP_COMMIT();
            CP_WAIT1();
        } else {
            CP_WAIT0();
        }
        __syncthreads();

#pragma unroll
        for (int ks = 0; ks < 32; ks += 16) {
            const uint32_t ab = bufb + a_off + (uint32_t)(ks * 2);
            const uint32_t bb = bufb + 2 * PROJ_TILE_B + b_off + (uint32_t)(ks * 2);

            uint32_t ah[4][4], bh[4][2], bl[4][2];
#pragma unroll
            for (int mt = 0; mt < 4; ++mt)
                LDSM_X4(ah[mt][0], ah[mt][1], ah[mt][2], ah[mt][3],
                        ab + (uint32_t)(mt * 1280));
#pragma unroll
            for (int nt = 0; nt < 4; ++nt)
                LDSM_X2(bh[nt][0], bh[nt][1], bb + (uint32_t)(nt * 640));
#pragma unroll
            for (int mt = 0; mt < 4; ++mt)
#pragma unroll
                for (int nt = 0; nt < 4; ++nt)
                    MMA_BF16(acc[mt][nt], ah[mt], bh[nt]);       // hi*hi
#pragma unroll
            for (int nt = 0; nt < 4; ++nt)
                LDSM_X2(bl[nt][0], bl[nt][1],
                        bb + (uint32_t)(PROJ_TILE_B + nt * 640));
#pragma unroll
            for (int mt = 0; mt < 4; ++mt)
#pragma unroll
                for (int nt = 0; nt < 4; ++nt)
                    MMA_BF16(acc[mt][nt], ah[mt], bl[nt]);       // hi*lo
#pragma unroll
            for (int mt = 0; mt < 4; ++mt)
                LDSM_X4(ah[mt][0], ah[mt][1], ah[mt][2], ah[mt][3],
                        ab + (uint32_t)(PROJ_TILE_B + mt * 1280));
#pragma unroll
            for (int mt = 0; mt < 4; ++mt)
#pragma unroll
                for (int nt = 0; nt < 4; ++nt)
                    MMA_BF16(acc[mt][nt], ah[mt], bh[nt]);       // lo*hi
        }
        __syncthreads();
    }

    // Epilogue: bias add + scatter to [b][h][s][hd]
    const int g  = lane >> 2;
    const int t2 = (lane & 3) * 2;
#pragma unroll
    for (int mt = 0; mt < 4; ++mt) {
        const int r0 = row0 + wm * 64 + mt * 16 + g;
        const int r1 = r0 + 8;
        const int bat0 = r0 >> 11, s0 = r0 & 2047;
        const int bat1 = r1 >> 11, s1 = r1 & 2047;
#pragma unroll
        for (int nt = 0; nt < 4; ++nt) {
            const int col = col0 + wn * 32 + nt * 8 + t2;
            const float2 bv = *(const float2*)(bias + col);
            const int h = col >> 6, hd = col & 63;
            float2 v0, v1;
            v0.x = acc[mt][nt][0] + bv.x; v0.y = acc[mt][nt][1] + bv.y;
            v1.x = acc[mt][nt][2] + bv.x; v1.y = acc[mt][nt][3] + bv.y;
            *(float2*)(out + ((size_t)(bat0 * H_ + h) * S_ + s0) * HD_ + hd) = v0;
            *(float2*)(out + ((size_t)(bat1 * H_ + h) * S_ + s1) * HD_ + hd) = v1;
        }
    }
}

// ---------------------------------------------------------------------------
// Flash attention, fp32. BR=128, BC=64, 256 threads (16x16), 8x4 micro-tile.
// Kt stride 68 -> vectorized float4 B-operand loads in the QK loop.
// ---------------------------------------------------------------------------
#define SMEM_FLOATS (64 * 128 + 64 * 68 + 64 * 64 + 64 * 129)

__device__ __forceinline__ float grp_max16(float v) {
    v = fmaxf(v, __shfl_xor_sync(0xffffffffu, v, 1));
    v = fmaxf(v, __shfl_xor_sync(0xffffffffu, v, 2));
    v = fmaxf(v, __shfl_xor_sync(0xffffffffu, v, 4));
    v = fmaxf(v, __shfl_xor_sync(0xffffffffu, v, 8));
    return v;
}
__device__ __forceinline__ float grp_sum16(float v) {
    v += __shfl_xor_sync(0xffffffffu, v, 1);
    v += __shfl_xor_sync(0xffffffffu, v, 2);
    v += __shfl_xor_sync(0xffffffffu, v, 4);
    v += __shfl_xor_sync(0xffffffffu, v, 8);
    return v;
}

__global__ __launch_bounds__(256)
void attn_kernel(float* __restrict__ out)
{
    extern __shared__ float sm[];
    float* Qt = sm;                 // [64 hd][128 rows], stride 128
    float* Kt = Qt + 64 * 128;      // [64 hd][64 keys],  stride 68 (float4 loads)
    float* Vs = Kt + 64 * 68;       // [64 keys][64 hd]
    float* Pt = Vs + 64 * 64;       // [64 keys][128 rows], stride 129

    const int tid = threadIdx.x;
    const int tx  = tid & 15;
    const int ty  = tid >> 4;
    const int bh  = blockIdx.y;
    const int q0  = blockIdx.x * 128;

    const float* qp = g_q + (size_t)bh * S_ * HD_;
    const float* kp = g_k + (size_t)bh * S_ * HD_;
    const float* vp = g_v + (size_t)bh * S_ * HD_;

#pragma unroll
    for (int m = 0; m < 8; ++m) {
        int idx = m * 256 + tid;
        int r   = idx >> 4;
        int c   = (idx & 15) << 2;
        float4 val = *(const float4*)(qp + (size_t)(q0 + r) * HD_ + c);
        Qt[(c + 0) * 128 + r] = val.x * 0.125f;
        Qt[(c + 1) * 128 + r] = val.y * 0.125f;
        Qt[(c + 2) * 128 + r] = val.z * 0.125f;
        Qt[(c + 3) * 128 + r] = val.w * 0.125f;
    }

    float m_i[8], l_i[8], O[8][4];
#pragma unroll
    for (int i = 0; i < 8; ++i) {
        m_i[i] = -1e30f; l_i[i] = 0.f;
        O[i][0] = O[i][1] = O[i][2] = O[i][3] = 0.f;
    }

    for (int kt = 0; kt < S_ / 64; ++kt) {
        __syncthreads();
        const int kb = kt * 64;
#pragma unroll
        for (int m = 0; m < 4; ++m) {
            int idx = m * 256 + tid;
            int key = idx >> 4;
            int c   = (idx & 15) << 2;
            float4 kv = *(const float4*)(kp + (size_t)(kb + key) * HD_ + c);
            Kt[(c + 0) * 68 + key] = kv.x;
            Kt[(c + 1) * 68 + key] = kv.y;
            Kt[(c + 2) * 68 + key] = kv.z;
            Kt[(c + 3) * 68 + key] = kv.w;
            float4 vv = *(const float4*)(vp + (size_t)(kb + key) * HD_ + c);
            *(float4*)&Vs[key * 64 + c] = vv;
        }
        __syncthreads();

        float sc[8][4];
#pragma unroll
        for (int i = 0; i < 8; ++i)
            sc[i][0] = sc[i][1] = sc[i][2] = sc[i][3] = 0.f;

#pragma unroll 4
        for (int kk = 0; kk < 64; ++kk) {
            float a[8], b[4];
            *(float4*)(a)     = *(const float4*)&Qt[kk * 128 + ty * 8];
            *(float4*)(a + 4) = *(const float4*)&Qt[kk * 128 + ty * 8 + 4];
            *(float4*)(b)     = *(const float4*)&Kt[kk * 68 + tx * 4];
#pragma unroll
            for (int i = 0; i < 8; ++i)
#pragma unroll
                for (int j = 0; j < 4; ++j)
                    sc[i][j] = fmaf(a[i], b[j], sc[i][j]);
        }

#pragma unroll
        for (int i = 0; i < 8; ++i) {
            float mx = fmaxf(fmaxf(sc[i][0], sc[i][1]), fmaxf(sc[i][2], sc[i][3]));
            mx = grp_max16(mx);
            float mnew = fmaxf(m_i[i], mx);
            float corr = __expf(m_i[i] - mnew);
            float rs = 0.f;
#pragma unroll
            for (int j = 0; j < 4; ++j) {
                float p = __expf(sc[i][j] - mnew);
                sc[i][j] = p;
                rs += p;
            }
            rs = grp_sum16(rs);
            l_i[i] = l_i[i] * corr + rs;
            m_i[i] = mnew;
            O[i][0] *= corr; O[i][1] *= corr; O[i][2] *= corr; O[i][3] *= corr;
        }

#pragma unroll
        for (int j = 0; j < 4; ++j)
#pragma unroll
            for (int i = 0; i < 8; ++i)
                Pt[(tx * 4 + j) * 129 + ty * 8 + i] = sc[i][j];
        __syncthreads();

#pragma unroll 4
        for (int kk = 0; kk < 64; ++kk) {
            float a[8], b[4];
            *(float4*)b = *(const float4*)&Vs[kk * 64 + tx * 4];
#pragma unroll
            for (int i = 0; i < 8; ++i) a[i] = Pt[kk * 129 + ty * 8 + i];
#pragma unroll
            for (int i = 0; i < 8; ++i)
#pragma unroll
                for (int j = 0; j < 4; ++j)
                    O[i][j] = fmaf(a[i], b[j], O[i][j]);
        }
    }

    const int bat = bh >> 4;
    const int h   = bh & 15;
#pragma unroll
    for (int i = 0; i < 8; ++i) {
        int s = q0 + ty * 8 + i;
        float inv = 1.0f / l_i[i];
        float4 o;
        o.x = O[i][0] * inv; o.y = O[i][1] * inv;
        o.z = O[i][2] * inv; o.w = O[i][3] * inv;
        *(float4*)(out + (size_t)(bat * S_ + s) * DM + h * HD_ + tx * 4) = o;
    }
}

// ---------------------------------------------------------------------------
extern "C" void kernel_launch(void* const* d_in, const int* in_sizes, int n_in,
                              void* d_out, int out_size)
{
    (void)in_sizes; (void)n_in; (void)out_size;
    const float* Q  = (const float*)d_in[0];
    const float* V  = (const float*)d_in[1];
    const float* K  = (const float*)d_in[2];
    const float* wq = (const float*)d_in[3];
    const float* bq = (const float*)d_in[4];
    const float* wk = (const float*)d_in[5];
    const float* bk = (const float*)d_in[6];
    const float* wv = (const float*)d_in[7];
    const float* bv = (const float*)d_in[8];
    float* out = (float*)d_out;

    // fp32 -> bf16 hi/lo conversion
    int nx = (MX * DIN) / 4 / 256;          // 8192 blocks
    conv_x_kernel<<<nx, 256>>>(Q, 0);
    conv_x_kernel<<<nx, 256>>>(K, 1);
    conv_x_kernel<<<nx, 256>>>(V, 2);
    dim3 wg(DM / 32, DIN / 32);             // (32, 32)
    conv_w_kernel<<<wg, 256>>>(wq, 0);
    conv_w_kernel<<<wg, 256>>>(wk, 1);
    conv_w_kernel<<<wg, 256>>>(wv, 2);

    // HMMA projections
    cudaFuncSetAttribute(proj_mma_kernel, cudaFuncAttributeMaxDynamicSharedMemorySize, PROJ_SMEM);
    dim3 pg(DM / 128, MX / 128);            // (8, 64)
    proj_mma_kernel<<<pg, 256, PROJ_SMEM>>>(bq, 0);
    proj_mma_kernel<<<pg, 256, PROJ_SMEM>>>(bk, 1);
    proj_mma_kernel<<<pg, 256, PROJ_SMEM>>>(bv, 2);

    // fp32 flash attention
    int smem = SMEM_FLOATS * (int)sizeof(float);
    cudaFuncSetAttribute(attn_kernel, cudaFuncAttributeMaxDynamicSharedMemorySize, smem);
    dim3 ag(S_ / 128, B_ * H_);             // (16, 64)
    attn_kernel<<<ag, 256, smem>>>(out);
}

// round 4
// speedup vs baseline: 2.0003x; 1.5544x over previous
#include <cuda_runtime.h>
#include <cuda_bf16.h>
#include <cstdint>

#define B_   4
#define S_   2048
#define DIN  1024
#define DM   1024
#define H_   16
#define HD_  64
#define MX   (B_ * S_)   // 8192

// ---------------- scratch (static device arrays: no allocs) ----------------
// bf16-split GEMM operands: X [M][K], W^T [N][K]
__device__ __nv_bfloat16 g_xhi[3][(size_t)MX * DIN];
__device__ __nv_bfloat16 g_xlo[3][(size_t)MX * DIN];
__device__ __nv_bfloat16 g_whi[3][(size_t)DM * DIN];
__device__ __nv_bfloat16 g_wlo[3][(size_t)DM * DIN];
// projected tensors, bf16 hi/lo split. q/k: [bh][s][hd]; v transposed: [bh][hd][s]
__device__ __nv_bfloat16 g_qhi[(size_t)64 * S_ * HD_];
__device__ __nv_bfloat16 g_qlo[(size_t)64 * S_ * HD_];
__device__ __nv_bfloat16 g_khi[(size_t)64 * S_ * HD_];
__device__ __nv_bfloat16 g_klo[(size_t)64 * S_ * HD_];
__device__ __nv_bfloat16 g_vthi[(size_t)64 * HD_ * S_];
__device__ __nv_bfloat16 g_vtlo[(size_t)64 * HD_ * S_];

// ---------------- PTX helpers (baseline sm_80-class ISA only) --------------
__device__ __forceinline__ uint32_t smem_u32(const void* p) {
    uint32_t a;
    asm("{ .reg .u64 t; cvta.to.shared.u64 t, %1; cvt.u32.u64 %0, t; }"
        : "=r"(a) : "l"(p));
    return a;
}

#define CP16(dst, src) \
    asm volatile("cp.async.cg.shared.global [%0], [%1], 16;" \
                 :: "r"(dst), "l"(src) : "memory")
#define CP_COMMIT() asm volatile("cp.async.commit_group;" ::: "memory")
#define CP_WAIT1()  asm volatile("cp.async.wait_group 1;" ::: "memory")
#define CP_WAIT0()  asm volatile("cp.async.wait_group 0;" ::: "memory")

#define LDSM_X4(r0, r1, r2, r3, a) \
    asm volatile("ldmatrix.sync.aligned.m8n8.x4.shared.b16 {%0,%1,%2,%3}, [%4];" \
                 : "=r"(r0), "=r"(r1), "=r"(r2), "=r"(r3) : "r"(a))
#define LDSM_X2(r0, r1, a) \
    asm volatile("ldmatrix.sync.aligned.m8n8.x2.shared.b16 {%0,%1}, [%2];" \
                 : "=r"(r0), "=r"(r1) : "r"(a))

#define MMA_BF16(c, a, b) \
    asm volatile("mma.sync.aligned.m16n8k16.row.col.f32.bf16.bf16.f32 " \
                 "{%0,%1,%2,%3}, {%4,%5,%6,%7}, {%8,%9}, {%0,%1,%2,%3};" \
                 : "+f"((c)[0]), "+f"((c)[1]), "+f"((c)[2]), "+f"((c)[3]) \
                 : "r"((a)[0]), "r"((a)[1]), "r"((a)[2]), "r"((a)[3]), \
                   "r"((b)[0]), "r"((b)[1]))
#define MMA_BF16S(c, a, b0v, b1v) \
    asm volatile("mma.sync.aligned.m16n8k16.row.col.f32.bf16.bf16.f32 " \
                 "{%0,%1,%2,%3}, {%4,%5,%6,%7}, {%8,%9}, {%0,%1,%2,%3};" \
                 : "+f"((c)[0]), "+f"((c)[1]), "+f"((c)[2]), "+f"((c)[3]) \
                 : "r"((a)[0]), "r"((a)[1]), "r"((a)[2]), "r"((a)[3]), \
                   "r"(b0v), "r"(b1v))

#define SWZ(x) ((uint32_t)(x) ^ ((((uint32_t)(x)) >> 3) & 0x70))

// fast e^x on the FMA pipe (x <= 0 path; clamped)
__device__ __forceinline__ float fexp(float x) {
    float y = x * 1.44269504f;
    y = fmaxf(y, -100.f);
    float t = y + 12582912.0f;           // round-to-nearest integer
    float nf = t - 12582912.0f;
    float f = y - nf;                    // f in [-0.5, 0.5]
    uint32_t sc = (__float_as_uint(t) << 23) + 0x3F800000u;  // 2^n
    float p = fmaf(f, 0.0096181291f, 0.0555041087f);
    p = fmaf(f, p, 0.2402265069f);
    p = fmaf(f, p, 0.6931471806f);
    p = fmaf(f, p, 1.0f);
    return p * __uint_as_float(sc);
}

__device__ __forceinline__ uint32_t packbf(float x, float y) {
    __nv_bfloat162 h = __float22bfloat162_rn(make_float2(x, y));
    return *(uint32_t*)&h;
}

// ---------------------------------------------------------------------------
// fp32 -> bf16 hi/lo split for X inputs
// ---------------------------------------------------------------------------
__global__ __launch_bounds__(256)
void conv_x_kernel(const float* __restrict__ X, int slot)
{
    size_t i = (size_t)blockIdx.x * 256 + threadIdx.x;
    float4 v = ((const float4*)X)[i];
    __nv_bfloat16 h0 = __float2bfloat16(v.x), h1 = __float2bfloat16(v.y);
    __nv_bfloat16 h2 = __float2bfloat16(v.z), h3 = __float2bfloat16(v.w);
    __nv_bfloat16 l0 = __float2bfloat16(v.x - __bfloat162float(h0));
    __nv_bfloat16 l1 = __float2bfloat16(v.y - __bfloat162float(h1));
    __nv_bfloat16 l2 = __float2bfloat16(v.z - __bfloat162float(h2));
    __nv_bfloat16 l3 = __float2bfloat16(v.w - __bfloat162float(h3));
    __nv_bfloat162* hp = reinterpret_cast<__nv_bfloat162*>(g_xhi[slot] + i * 4);
    __nv_bfloat162* lp = reinterpret_cast<__nv_bfloat162*>(g_xlo[slot] + i * 4);
    __nv_bfloat162 a; a.x = h0; a.y = h1; hp[0] = a;
    __nv_bfloat162 b; b.x = h2; b.y = h3; hp[1] = b;
    __nv_bfloat162 c; c.x = l0; c.y = l1; lp[0] = c;
    __nv_bfloat162 d; d.x = l2; d.y = l3; lp[1] = d;
}

// ---------------------------------------------------------------------------
// W [K][N] fp32 -> transposed [N][K] bf16 hi/lo
// ---------------------------------------------------------------------------
__global__ __launch_bounds__(256)
void conv_w_kernel(const float* __restrict__ W, int slot)
{
    __shared__ float t[32][33];
    const int n0 = blockIdx.x * 32, k0 = blockIdx.y * 32;
    const int tx = threadIdx.x & 31, ty = threadIdx.x >> 5;
#pragma unroll
    for (int r = 0; r < 32; r += 8)
        t[ty + r][tx] = W[(size_t)(k0 + ty + r) * DM + n0 + tx];
    __syncthreads();
#pragma unroll
    for (int r = 0; r < 32; r += 8) {
        int n = ty + r;
        float x = t[tx][n];
        __nv_bfloat16 h = __float2bfloat16(x);
        float l = x - __bfloat162float(h);
        size_t o = (size_t)(n0 + n) * DIN + k0 + tx;
        g_whi[slot][o] = h;
        g_wlo[slot][o] = __float2bfloat16(l);
    }
}

// ---------------------------------------------------------------------------
// HMMA projection GEMM (mainloop from R3). Epilogue writes bf16 hi/lo:
// which==0: q (scaled 0.125) -> g_qhi/lo [bh][s][hd]
// which==1: k              -> g_khi/lo [bh][s][hd]
// which==2: v transposed   -> g_vthi/lo [bh][hd][s]
// ---------------------------------------------------------------------------
#define PROJ_TILE_B   10240
#define PROJ_BUF_B    (4 * PROJ_TILE_B)
#define PROJ_SMEM     (2 * PROJ_BUF_B)

__global__ __launch_bounds__(256)
void proj_mma_kernel(const float* __restrict__ bias, int which)
{
    extern __shared__ char dsm[];
    const uint32_t sbase = smem_u32(dsm);

    const __nv_bfloat16* Ah = g_xhi[which];
    const __nv_bfloat16* Al = g_xlo[which];
    const __nv_bfloat16* Bh = g_whi[which];
    const __nv_bfloat16* Bl = g_wlo[which];

    const int tid  = threadIdx.x;
    const int wid  = tid >> 5, lane = tid & 31;
    const int wm   = wid & 1;
    const int wn   = wid >> 1;
    const int row0 = blockIdx.y * 128, col0 = blockIdx.x * 128;

    const int lrow  = tid >> 1;
    const int lhalf = tid & 1;
    const uint32_t sdst = (uint32_t)(lrow * 80 + lhalf * 32);
    const char* gA_h = (const char*)(Ah + (size_t)(row0 + lrow) * DIN) + lhalf * 32;
    const char* gA_l = (const char*)(Al + (size_t)(row0 + lrow) * DIN) + lhalf * 32;
    const char* gB_h = (const char*)(Bh + (size_t)(col0 + lrow) * DIN) + lhalf * 32;
    const char* gB_l = (const char*)(Bl + (size_t)(col0 + lrow) * DIN) + lhalf * 32;

    const int r8 = lane & 7;
    const int ami = lane >> 3;
    const uint32_t a_off = (uint32_t)(((wm * 64 + (ami & 1) * 8 + r8) * 40
                                       + (ami >> 1) * 8) * 2);
    const int bmi = (lane >> 3) & 1;
    const uint32_t b_off = (uint32_t)(((wn * 32 + r8) * 40 + bmi * 8) * 2);

    float acc[4][4][4];
#pragma unroll
    for (int i = 0; i < 4; ++i)
#pragma unroll
        for (int j = 0; j < 4; ++j)
            acc[i][j][0] = acc[i][j][1] = acc[i][j][2] = acc[i][j][3] = 0.f;

    {
        uint32_t b0 = sbase;
        CP16(b0 + sdst,                    gA_h);
        CP16(b0 + sdst + 16,               gA_h + 16);
        CP16(b0 + PROJ_TILE_B + sdst,      gA_l);
        CP16(b0 + PROJ_TILE_B + sdst + 16, gA_l + 16);
        CP16(b0 + 2 * PROJ_TILE_B + sdst,      gB_h);
        CP16(b0 + 2 * PROJ_TILE_B + sdst + 16, gB_h + 16);
        CP16(b0 + 3 * PROJ_TILE_B + sdst,      gB_l);
        CP16(b0 + 3 * PROJ_TILE_B + sdst + 16, gB_l + 16);
        CP_COMMIT();
    }

    for (int c = 0; c < 32; ++c) {
        const uint32_t bufb = sbase + (uint32_t)(c & 1) * PROJ_BUF_B;
        if (c + 1 < 32) {
            const uint32_t nb = sbase + (uint32_t)((c + 1) & 1) * PROJ_BUF_B;
            const int kb = (c + 1) * 64;
            CP16(nb + sdst,                    gA_h + kb);
            CP16(nb + sdst + 16,               gA_h + kb + 16);
            CP16(nb + PROJ_TILE_B + sdst,      gA_l + kb);
            CP16(nb + PROJ_TILE_B + sdst + 16, gA_l + kb + 16);
            CP16(nb + 2 * PROJ_TILE_B + sdst,      gB_h + kb);
            CP16(nb + 2 * PROJ_TILE_B + sdst + 16, gB_h + kb + 16);
            CP16(nb + 3 * PROJ_TILE_B + sdst,      gB_l + kb);
            CP16(nb + 3 * PROJ_TILE_B + sdst + 16, gB_l + kb + 16);
            CP_COMMIT();
            CP_WAIT1();
        } else {
            CP_WAIT0();
        }
        __syncthreads();

#pragma unroll
        for (int ks = 0; ks < 32; ks += 16) {
            const uint32_t ab = bufb + a_off + (uint32_t)(ks * 2);
            const uint32_t bb = bufb + 2 * PROJ_TILE_B + b_off + (uint32_t)(ks * 2);

            uint32_t ah[4][4], bhf[4][2], blf[4][2];
#pragma unroll
            for (int mt = 0; mt < 4; ++mt)
                LDSM_X4(ah[mt][0], ah[mt][1], ah[mt][2], ah[mt][3],
                        ab + (uint32_t)(mt * 1280));
#pragma unroll
            for (int nt = 0; nt < 4; ++nt)
                LDSM_X2(bhf[nt][0], bhf[nt][1], bb + (uint32_t)(nt * 640));
#pragma unroll
            for (int mt = 0; mt < 4; ++mt)
#pragma unroll
                for (int nt = 0; nt < 4; ++nt)
                    MMA_BF16(acc[mt][nt], ah[mt], bhf[nt]);
#pragma unroll
            for (int nt = 0; nt < 4; ++nt)
                LDSM_X2(blf[nt][0], blf[nt][1],
                        bb + (uint32_t)(PROJ_TILE_B + nt * 640));
#pragma unroll
            for (int mt = 0; mt < 4; ++mt)
#pragma unroll
                for (int nt = 0; nt < 4; ++nt)
                    MMA_BF16(acc[mt][nt], ah[mt], blf[nt]);
#pragma unroll
            for (int mt = 0; mt < 4; ++mt)
                LDSM_X4(ah[mt][0], ah[mt][1], ah[mt][2], ah[mt][3],
                        ab + (uint32_t)(PROJ_TILE_B + mt * 1280));
#pragma unroll
            for (int mt = 0; mt < 4; ++mt)
#pragma unroll
                for (int nt = 0; nt < 4; ++nt)
                    MMA_BF16(acc[mt][nt], ah[mt], bhf[nt]);
        }
        __syncthreads();
    }

    // Epilogue: bias, optional 1/8 scale, hi/lo split, scatter
    const int g  = lane >> 2;
    const int t2 = (lane & 3) * 2;
    const float scale = (which == 0) ? 0.125f : 1.0f;
#pragma unroll
    for (int mt = 0; mt < 4; ++mt) {
        const int r0 = row0 + wm * 64 + mt * 16 + g;
        const int r1 = r0 + 8;
        const int bat = r0 >> 11;             // r1 same batch (r0%2048 <= 2039)
        const int s0 = r0 & 2047, s1 = r1 & 2047;
#pragma unroll
        for (int nt = 0; nt < 4; ++nt) {
            const int col = col0 + wn * 32 + nt * 8 + t2;
            const float2 bv = *(const float2*)(bias + col);
            const int h = col >> 6, hd = col & 63;
            const int bh = bat * H_ + h;
            float v00 = (acc[mt][nt][0] + bv.x) * scale;
            float v01 = (acc[mt][nt][1] + bv.y) * scale;
            float v10 = (acc[mt][nt][2] + bv.x) * scale;
            float v11 = (acc[mt][nt][3] + bv.y) * scale;
            if (which < 2) {
                __nv_bfloat16* dh = (which == 0 ? g_qhi : g_khi);
                __nv_bfloat16* dl = (which == 0 ? g_qlo : g_klo);
                size_t o0 = ((size_t)bh * S_ + s0) * HD_ + hd;
                size_t o1 = ((size_t)bh * S_ + s1) * HD_ + hd;
                uint32_t h0 = packbf(v00, v01), h1 = packbf(v10, v11);
                __nv_bfloat162 hh0 = *(__nv_bfloat162*)&h0;
                __nv_bfloat162 hh1 = *(__nv_bfloat162*)&h1;
                float2 f0 = __bfloat1622float2(hh0);
                float2 f1 = __bfloat1622float2(hh1);
                uint32_t l0v = packbf(v00 - f0.x, v01 - f0.y);
                uint32_t l1v = packbf(v10 - f1.x, v11 - f1.y);
                *(uint32_t*)(dh + o0) = h0;
                *(uint32_t*)(dh + o1) = h1;
                *(uint32_t*)(dl + o0) = l0v;
                *(uint32_t*)(dl + o1) = l1v;
            } else {
                size_t base0 = ((size_t)bh * HD_ + hd) * S_;
                size_t base1 = base0 + S_;   // hd+1 row
                __nv_bfloat16 h00 = __float2bfloat16(v00);
                __nv_bfloat16 h01 = __float2bfloat16(v01);
                __nv_bfloat16 h10 = __float2bfloat16(v10);
                __nv_bfloat16 h11 = __float2bfloat16(v11);
                g_vthi[base0 + s0] = h00;
                g_vthi[base1 + s0] = h01;
                g_vthi[base0 + s1] = h10;
                g_vthi[base1 + s1] = h11;
                g_vtlo[base0 + s0] = __float2bfloat16(v00 - __bfloat162float(h00));
                g_vtlo[base1 + s0] = __float2bfloat16(v01 - __bfloat162float(h01));
                g_vtlo[base0 + s1] = __float2bfloat16(v10 - __bfloat162float(h10));
                g_vtlo[base1 + s1] = __float2bfloat16(v11 - __bfloat162float(h11));
            }
        }
    }
}

// ---------------------------------------------------------------------------
// HMMA flash attention. BR=128, BC=64, 8 warps. 3-term bf16 split on both
// GEMMs; Q in registers; P reused as A fragments; V pre-transposed.
// smem: double buffer of {Khi,Klo,Vthi,Vtlo} 8KB tiles = 2x32KB (+align pad)
// ---------------------------------------------------------------------------
#define ATTN_SMEM (65536 + 1024)

__global__ __launch_bounds__(256)
void attn_mma_kernel(float* __restrict__ out)
{
    extern __shared__ char asmem[];
    const uint32_t sb = (smem_u32(asmem) + 1023u) & ~1023u;

    const int tid  = threadIdx.x;
    const int lane = tid & 31, warp = tid >> 5;
    const int bh   = blockIdx.y;
    const int q0   = blockIdx.x * 128;

    const __nv_bfloat16* qh = g_qhi + (size_t)bh * S_ * HD_;
    const __nv_bfloat16* ql = g_qlo + (size_t)bh * S_ * HD_;
    const char* kh = (const char*)(g_khi + (size_t)bh * S_ * HD_);
    const char* kl = (const char*)(g_klo + (size_t)bh * S_ * HD_);
    const char* vh = (const char*)(g_vthi + (size_t)bh * HD_ * S_);
    const char* vl = (const char*)(g_vtlo + (size_t)bh * HD_ * S_);

    // ldmatrix per-lane address components (x4, A-style 16x16)
    const int r8 = lane & 7;
    const int arow = ((lane >> 3) & 1) * 8 + r8;
    const int acol = lane >> 4;              // 16B-chunk offset 0/1

    // ---- stage Q tile [128][64] hi/lo into buf1 region, chunk0 into buf0 ----
    {
        int row = tid >> 1, c0 = (tid & 1) * 4;
        const char* sh = (const char*)(qh + (size_t)(q0 + row) * HD_) + c0 * 16;
        const char* sl = (const char*)(ql + (size_t)(q0 + row) * HD_) + c0 * 16;
#pragma unroll
        for (int i = 0; i < 4; ++i) {
            uint32_t off = SWZ(row * 128 + (c0 + i) * 16);
            CP16(sb + 32768 + off, sh + i * 16);
            CP16(sb + 49152 + off, sl + i * 16);
        }
        CP_COMMIT();
    }
    {
        int row = tid >> 2, c0 = (tid & 3) * 2;   // 64 rows, 2 chunks each
#pragma unroll
        for (int i = 0; i < 2; ++i) {
            int c = c0 + i;
            uint32_t off = SWZ(row * 128 + c * 16);
            CP16(sb + off,         kh + row * 128 + c * 16);
            CP16(sb + 8192 + off,  kl + row * 128 + c * 16);
            CP16(sb + 16384 + off, vh + (size_t)row * (S_ * 2) + c * 16);
            CP16(sb + 24576 + off, vl + (size_t)row * (S_ * 2) + c * 16);
        }
        CP_COMMIT();
    }
    CP_WAIT0();
    __syncthreads();

    // ---- Q fragments into registers ----
    uint32_t qa_h[4][4], qa_l[4][4];
#pragma unroll
    for (int ks = 0; ks < 4; ++ks) {
        int row = warp * 16 + arow;
        int ch  = ks * 2 + acol;
        uint32_t off = SWZ(row * 128 + ch * 16);
        LDSM_X4(qa_h[ks][0], qa_h[ks][1], qa_h[ks][2], qa_h[ks][3], sb + 32768 + off);
        LDSM_X4(qa_l[ks][0], qa_l[ks][1], qa_l[ks][2], qa_l[ks][3], sb + 49152 + off);
    }
    __syncthreads();   // all warps done reading buf1 (Q staging)

    float m0 = -1e30f, m1 = -1e30f, l0 = 0.f, l1 = 0.f;
    float o[8][4];
#pragma unroll
    for (int nt = 0; nt < 8; ++nt)
        o[nt][0] = o[nt][1] = o[nt][2] = o[nt][3] = 0.f;

    for (int c = 0; c < 32; ++c) {
        if (c > 0) CP_WAIT0();
        __syncthreads();         // chunk c visible; prev compute done everywhere
        if (c + 1 < 32) {
            const uint32_t nb = sb + (uint32_t)((c + 1) & 1) * 32768;
            const int kb = (c + 1) * 64;
            int row = tid >> 2, c0 = (tid & 3) * 2;
#pragma unroll
            for (int i = 0; i < 2; ++i) {
                int ch = c0 + i;
                uint32_t off = SWZ(row * 128 + ch * 16);
                CP16(nb + off,         kh + (size_t)(kb + row) * 128 + ch * 16);
                CP16(nb + 8192 + off,  kl + (size_t)(kb + row) * 128 + ch * 16);
                CP16(nb + 16384 + off, vh + (size_t)row * (S_ * 2) + kb * 2 + ch * 16);
                CP16(nb + 24576 + off, vl + (size_t)row * (S_ * 2) + kb * 2 + ch * 16);
            }
            CP_COMMIT();
        }
        const uint32_t buf = sb + (uint32_t)(c & 1) * 32768;

        // ---- S = Q @ K^T (3-term split) ----
        float cc[8][4];
#pragma unroll
        for (int nt = 0; nt < 8; ++nt)
            cc[nt][0] = cc[nt][1] = cc[nt][2] = cc[nt][3] = 0.f;

#pragma unroll
        for (int ks = 0; ks < 4; ++ks) {
#pragma unroll
            for (int np = 0; np < 4; ++np) {
                int row = np * 16 + arow;
                int ch  = ks * 2 + acol;
                uint32_t off = SWZ(row * 128 + ch * 16);
                uint32_t b0, b1, b2, b3;
                LDSM_X4(b0, b1, b2, b3, buf + off);            // K hi
                MMA_BF16S(cc[2 * np],     qa_h[ks], b0, b2);
                MMA_BF16S(cc[2 * np + 1], qa_h[ks], b1, b3);
                MMA_BF16S(cc[2 * np],     qa_l[ks], b0, b2);
                MMA_BF16S(cc[2 * np + 1], qa_l[ks], b1, b3);
                LDSM_X4(b0, b1, b2, b3, buf + 8192 + off);     // K lo
                MMA_BF16S(cc[2 * np],     qa_h[ks], b0, b2);
                MMA_BF16S(cc[2 * np + 1], qa_h[ks], b1, b3);
            }
        }

        // ---- online softmax (rows g and g+8) ----
        float rmx0 = cc[0][0], rmx1 = cc[0][2];
#pragma unroll
        for (int nt = 0; nt < 8; ++nt) {
            rmx0 = fmaxf(rmx0, fmaxf(cc[nt][0], cc[nt][1]));
            rmx1 = fmaxf(rmx1, fmaxf(cc[nt][2], cc[nt][3]));
        }
        rmx0 = fmaxf(rmx0, __shfl_xor_sync(0xffffffffu, rmx0, 1));
        rmx0 = fmaxf(rmx0, __shfl_xor_sync(0xffffffffu, rmx0, 2));
        rmx1 = fmaxf(rmx1, __shfl_xor_sync(0xffffffffu, rmx1, 1));
        rmx1 = fmaxf(rmx1, __shfl_xor_sync(0xffffffffu, rmx1, 2));
        float mn0 = fmaxf(m0, rmx0), mn1 = fmaxf(m1, rmx1);
        float cr0 = fexp(m0 - mn0), cr1 = fexp(m1 - mn1);
        m0 = mn0; m1 = mn1;
        float rs0 = 0.f, rs1 = 0.f;
#pragma unroll
        for (int nt = 0; nt < 8; ++nt) {
            cc[nt][0] = fexp(cc[nt][0] - mn0);
            cc[nt][1] = fexp(cc[nt][1] - mn0);
            cc[nt][2] = fexp(cc[nt][2] - mn1);
            cc[nt][3] = fexp(cc[nt][3] - mn1);
            rs0 += cc[nt][0] + cc[nt][1];
            rs1 += cc[nt][2] + cc[nt][3];
        }
        rs0 += __shfl_xor_sync(0xffffffffu, rs0, 1);
        rs0 += __shfl_xor_sync(0xffffffffu, rs0, 2);
        rs1 += __shfl_xor_sync(0xffffffffu, rs1, 1);
        rs1 += __shfl_xor_sync(0xffffffffu, rs1, 2);
        l0 = l0 * cr0 + rs0;
        l1 = l1 * cr1 + rs1;
#pragma unroll
        for (int nt = 0; nt < 8; ++nt) {
            o[nt][0] *= cr0; o[nt][1] *= cr0;
            o[nt][2] *= cr1; o[nt][3] *= cr1;
        }

        // ---- pack P into A fragments (hi/lo) ----
        uint32_t pa_h[4][4], pa_l[4][4];
#pragma unroll
        for (int j = 0; j < 4; ++j) {
            float x0 = cc[2 * j][0],     x1 = cc[2 * j][1];
            float x2 = cc[2 * j][2],     x3 = cc[2 * j][3];
            float x4 = cc[2 * j + 1][0], x5 = cc[2 * j + 1][1];
            float x6 = cc[2 * j + 1][2], x7 = cc[2 * j + 1][3];
            uint32_t h0 = packbf(x0, x1), h1 = packbf(x2, x3);
            uint32_t h2 = packbf(x4, x5), h3 = packbf(x6, x7);
            pa_h[j][0] = h0; pa_h[j][1] = h1; pa_h[j][2] = h2; pa_h[j][3] = h3;
            float2 f0 = __bfloat1622float2(*(__nv_bfloat162*)&h0);
            float2 f1 = __bfloat1622float2(*(__nv_bfloat162*)&h1);
            float2 f2 = __bfloat1622float2(*(__nv_bfloat162*)&h2);
            float2 f3 = __bfloat1622float2(*(__nv_bfloat162*)&h3);
            pa_l[j][0] = packbf(x0 - f0.x, x1 - f0.y);
            pa_l[j][1] = packbf(x2 - f1.x, x3 - f1.y);
            pa_l[j][2] = packbf(x4 - f2.x, x5 - f2.y);
            pa_l[j][3] = packbf(x6 - f3.x, x7 - f3.y);
        }

        // ---- O += P @ V (3-term split) ----
#pragma unroll
        for (int j = 0; j < 4; ++j) {
#pragma unroll
            for (int np = 0; np < 4; ++np) {
                int row = np * 16 + arow;
                int ch  = j * 2 + acol;
                uint32_t off = SWZ(row * 128 + ch * 16);
                uint32_t b0, b1, b2, b3;
                LDSM_X4(b0, b1, b2, b3, buf + 16384 + off);    // V hi
                MMA_BF16S(o[2 * np],     pa_h[j], b0, b2);
                MMA_BF16S(o[2 * np + 1], pa_h[j], b1, b3);
                MMA_BF16S(o[2 * np],     pa_l[j], b0, b2);
                MMA_BF16S(o[2 * np + 1], pa_l[j], b1, b3);
                LDSM_X4(b0, b1, b2, b3, buf + 24576 + off);    // V lo
                MMA_BF16S(o[2 * np],     pa_h[j], b0, b2);
                MMA_BF16S(o[2 * np + 1], pa_h[j], b1, b3);
            }
        }
    }

    // ---- epilogue ----
    const int g  = lane >> 2;
    const int t2 = (lane & 3) * 2;
    const int bat = bh >> 4, h = bh & 15;
    const int s0 = q0 + warp * 16 + g, s1 = s0 + 8;
    const float inv0 = 1.0f / l0, inv1 = 1.0f / l1;
#pragma unroll
    for (int nt = 0; nt < 8; ++nt) {
        int col = h * HD_ + nt * 8 + t2;
        float2 v0, v1;
        v0.x = o[nt][0] * inv0; v0.y = o[nt][1] * inv0;
        v1.x = o[nt][2] * inv1; v1.y = o[nt][3] * inv1;
        *(float2*)(out + ((size_t)bat * S_ + s0) * DM + col) = v0;
        *(float2*)(out + ((size_t)bat * S_ + s1) * DM + col) = v1;
    }
}

// ---------------------------------------------------------------------------
extern "C" void kernel_launch(void* const* d_in, const int* in_sizes, int n_in,
                              void* d_out, int out_size)
{
    (void)in_sizes; (void)n_in; (void)out_size;
    const float* Q  = (const float*)d_in[0];
    const float* V  = (const float*)d_in[1];
    const float* K  = (const float*)d_in[2];
    const float* wq = (const float*)d_in[3];
    const float* bq = (const float*)d_in[4];
    const float* wk = (const float*)d_in[5];
    const float* bk = (const float*)d_in[6];
    const float* wv = (const float*)d_in[7];
    const float* bv = (const float*)d_in[8];
    float* out = (float*)d_out;

    int nx = (MX * DIN) / 4 / 256;
    conv_x_kernel<<<nx, 256>>>(Q, 0);
    conv_x_kernel<<<nx, 256>>>(K, 1);
    conv_x_kernel<<<nx, 256>>>(V, 2);
    dim3 wg(DM / 32, DIN / 32);
    conv_w_kernel<<<wg, 256>>>(wq, 0);
    conv_w_kernel<<<wg, 256>>>(wk, 1);
    conv_w_kernel<<<wg, 256>>>(wv, 2);

    cudaFuncSetAttribute(proj_mma_kernel, cudaFuncAttributeMaxDynamicSharedMemorySize, PROJ_SMEM);
    dim3 pg(DM / 128, MX / 128);
    proj_mma_kernel<<<pg, 256, PROJ_SMEM>>>(bq, 0);
    proj_mma_kernel<<<pg, 256, PROJ_SMEM>>>(bk, 1);
    proj_mma_kernel<<<pg, 256, PROJ_SMEM>>>(bv, 2);

    cudaFuncSetAttribute(attn_mma_kernel, cudaFuncAttributeMaxDynamicSharedMemorySize, ATTN_SMEM);
    dim3 ag(S_ / 128, B_ * H_);
    attn_mma_kernel<<<ag, 256, ATTN_SMEM>>>(out);
}

// round 5
// speedup vs baseline: 2.4279x; 1.2137x over previous
#include <cuda_runtime.h>
#include <cuda_bf16.h>
#include <cuda_fp16.h>
#include <cstdint>

#define B_   4
#define S_   2048
#define DIN  1024
#define DM   1024
#define H_   16
#define HD_  64
#define MX   (B_ * S_)   // 8192

// ---------------- scratch (static device arrays: no allocs) ----------------
__device__ __nv_bfloat16 g_xhi[3][(size_t)MX * DIN];
__device__ __nv_bfloat16 g_xlo[3][(size_t)MX * DIN];
__device__ __nv_bfloat16 g_whi[3][(size_t)DM * DIN];
__device__ __nv_bfloat16 g_wlo[3][(size_t)DM * DIN];
// projected tensors (fp16). q: hi/lo split, k: hi only, v: transposed hi/lo
__device__ __half g_qhi[(size_t)64 * S_ * HD_];
__device__ __half g_qlo[(size_t)64 * S_ * HD_];
__device__ __half g_kh [(size_t)64 * S_ * HD_];
__device__ __half g_vthi[(size_t)64 * HD_ * S_];
__device__ __half g_vtlo[(size_t)64 * HD_ * S_];

// ---------------- PTX helpers (baseline sm_80-class ISA only) --------------
__device__ __forceinline__ uint32_t smem_u32(const void* p) {
    uint32_t a;
    asm("{ .reg .u64 t; cvta.to.shared.u64 t, %1; cvt.u32.u64 %0, t; }"
        : "=r"(a) : "l"(p));
    return a;
}

#define CP16(dst, src) \
    asm volatile("cp.async.cg.shared.global [%0], [%1], 16;" \
                 :: "r"(dst), "l"(src) : "memory")
#define CP_COMMIT() asm volatile("cp.async.commit_group;" ::: "memory")
#define CP_WAIT1()  asm volatile("cp.async.wait_group 1;" ::: "memory")
#define CP_WAIT0()  asm volatile("cp.async.wait_group 0;" ::: "memory")

#define LDSM_X4(r0, r1, r2, r3, a) \
    asm volatile("ldmatrix.sync.aligned.m8n8.x4.shared.b16 {%0,%1,%2,%3}, [%4];" \
                 : "=r"(r0), "=r"(r1), "=r"(r2), "=r"(r3) : "r"(a))
#define LDSM_X2(r0, r1, a) \
    asm volatile("ldmatrix.sync.aligned.m8n8.x2.shared.b16 {%0,%1}, [%2];" \
                 : "=r"(r0), "=r"(r1) : "r"(a))

#define MMA_BF16(c, a, b) \
    asm volatile("mma.sync.aligned.m16n8k16.row.col.f32.bf16.bf16.f32 " \
                 "{%0,%1,%2,%3}, {%4,%5,%6,%7}, {%8,%9}, {%0,%1,%2,%3};" \
                 : "+f"((c)[0]), "+f"((c)[1]), "+f"((c)[2]), "+f"((c)[3]) \
                 : "r"((a)[0]), "r"((a)[1]), "r"((a)[2]), "r"((a)[3]), \
                   "r"((b)[0]), "r"((b)[1]))
#define MMA_F16S(c, a, b0v, b1v) \
    asm volatile("mma.sync.aligned.m16n8k16.row.col.f32.f16.f16.f32 " \
                 "{%0,%1,%2,%3}, {%4,%5,%6,%7}, {%8,%9}, {%0,%1,%2,%3};" \
                 : "+f"((c)[0]), "+f"((c)[1]), "+f"((c)[2]), "+f"((c)[3]) \
                 : "r"((a)[0]), "r"((a)[1]), "r"((a)[2]), "r"((a)[3]), \
                   "r"(b0v), "r"(b1v))

#define SWZ(x) ((uint32_t)(x) ^ ((((uint32_t)(x)) >> 3) & 0x70))

// fast e^x on the FMA pipe (x <= 0 path; clamped)
__device__ __forceinline__ float fexp(float x) {
    float y = x * 1.44269504f;
    y = fmaxf(y, -100.f);
    float t = y + 12582912.0f;
    float nf = t - 12582912.0f;
    float f = y - nf;
    uint32_t sc = (__float_as_uint(t) << 23) + 0x3F800000u;
    float p = fmaf(f, 0.0096181291f, 0.0555041087f);
    p = fmaf(f, p, 0.2402265069f);
    p = fmaf(f, p, 0.6931471806f);
    p = fmaf(f, p, 1.0f);
    return p * __uint_as_float(sc);
}

__device__ __forceinline__ uint32_t packhf(float x, float y) {
    __half2 h = __floats2half2_rn(x, y);
    return *(uint32_t*)&h;
}

// ---------------------------------------------------------------------------
// fp32 -> bf16 hi/lo split for X inputs. blockIdx.y selects slot.
// ---------------------------------------------------------------------------
__global__ __launch_bounds__(256)
void conv_x_kernel(const float* __restrict__ Q, const float* __restrict__ K,
                   const float* __restrict__ V)
{
    const int slot = blockIdx.y;
    const float* X = (slot == 0) ? Q : (slot == 1) ? K : V;
    size_t i = (size_t)blockIdx.x * 256 + threadIdx.x;
    float4 v = ((const float4*)X)[i];
    __nv_bfloat16 h0 = __float2bfloat16(v.x), h1 = __float2bfloat16(v.y);
    __nv_bfloat16 h2 = __float2bfloat16(v.z), h3 = __float2bfloat16(v.w);
    __nv_bfloat16 l0 = __float2bfloat16(v.x - __bfloat162float(h0));
    __nv_bfloat16 l1 = __float2bfloat16(v.y - __bfloat162float(h1));
    __nv_bfloat16 l2 = __float2bfloat16(v.z - __bfloat162float(h2));
    __nv_bfloat16 l3 = __float2bfloat16(v.w - __bfloat162float(h3));
    __nv_bfloat162* hp = reinterpret_cast<__nv_bfloat162*>(g_xhi[slot] + i * 4);
    __nv_bfloat162* lp = reinterpret_cast<__nv_bfloat162*>(g_xlo[slot] + i * 4);
    __nv_bfloat162 a; a.x = h0; a.y = h1; hp[0] = a;
    __nv_bfloat162 b; b.x = h2; b.y = h3; hp[1] = b;
    __nv_bfloat162 c; c.x = l0; c.y = l1; lp[0] = c;
    __nv_bfloat162 d; d.x = l2; d.y = l3; lp[1] = d;
}

// ---------------------------------------------------------------------------
// W [K][N] fp32 -> transposed [N][K] bf16 hi/lo. blockIdx.z selects slot.
// ---------------------------------------------------------------------------
__global__ __launch_bounds__(256)
void conv_w_kernel(const float* __restrict__ WQ, const float* __restrict__ WK,
                   const float* __restrict__ WV)
{
    __shared__ float t[32][33];
    const int slot = blockIdx.z;
    const float* W = (slot == 0) ? WQ : (slot == 1) ? WK : WV;
    const int n0 = blockIdx.x * 32, k0 = blockIdx.y * 32;
    const int tx = threadIdx.x & 31, ty = threadIdx.x >> 5;
#pragma unroll
    for (int r = 0; r < 32; r += 8)
        t[ty + r][tx] = W[(size_t)(k0 + ty + r) * DM + n0 + tx];
    __syncthreads();
#pragma unroll
    for (int r = 0; r < 32; r += 8) {
        int n = ty + r;
        float x = t[tx][n];
        __nv_bfloat16 h = __float2bfloat16(x);
        float l = x - __bfloat162float(h);
        size_t o = (size_t)(n0 + n) * DIN + k0 + tx;
        g_whi[slot][o] = h;
        g_wlo[slot][o] = __float2bfloat16(l);
    }
}

// ---------------------------------------------------------------------------
// HMMA projection GEMM (bf16 3-term). blockIdx.z = which. fp16 epilogue:
// which==0: q*0.125 -> g_qhi/qlo [bh][s][hd]
// which==1: k       -> g_kh (hi only)
// which==2: v       -> g_vthi/vtlo transposed [bh][hd][s]
// ---------------------------------------------------------------------------
#define PROJ_TILE_B   10240
#define PROJ_BUF_B    (4 * PROJ_TILE_B)
#define PROJ_SMEM     (2 * PROJ_BUF_B)

__global__ __launch_bounds__(256)
void proj_mma_kernel(const float* __restrict__ bq, const float* __restrict__ bk,
                     const float* __restrict__ bv)
{
    extern __shared__ char dsm[];
    const uint32_t sbase = smem_u32(dsm);

    const int which = blockIdx.z;
    const float* bias = (which == 0) ? bq : (which == 1) ? bk : bv;
    const __nv_bfloat16* Ah = g_xhi[which];
    const __nv_bfloat16* Al = g_xlo[which];
    const __nv_bfloat16* Bh = g_whi[which];
    const __nv_bfloat16* Bl = g_wlo[which];

    const int tid  = threadIdx.x;
    const int wid  = tid >> 5, lane = tid & 31;
    const int wm   = wid & 1;
    const int wn   = wid >> 1;
    const int row0 = blockIdx.y * 128, col0 = blockIdx.x * 128;

    const int lrow  = tid >> 1;
    const int lhalf = tid & 1;
    const uint32_t sdst = (uint32_t)(lrow * 80 + lhalf * 32);
    const char* gA_h = (const char*)(Ah + (size_t)(row0 + lrow) * DIN) + lhalf * 32;
    const char* gA_l = (const char*)(Al + (size_t)(row0 + lrow) * DIN) + lhalf * 32;
    const char* gB_h = (const char*)(Bh + (size_t)(col0 + lrow) * DIN) + lhalf * 32;
    const char* gB_l = (const char*)(Bl + (size_t)(col0 + lrow) * DIN) + lhalf * 32;

    const int r8 = lane & 7;
    const int ami = lane >> 3;
    const uint32_t a_off = (uint32_t)(((wm * 64 + (ami & 1) * 8 + r8) * 40
                                       + (ami >> 1) * 8) * 2);
    const int bmi = (lane >> 3) & 1;
    const uint32_t b_off = (uint32_t)(((wn * 32 + r8) * 40 + bmi * 8) * 2);

    float acc[4][4][4];
#pragma unroll
    for (int i = 0; i < 4; ++i)
#pragma unroll
        for (int j = 0; j < 4; ++j)
            acc[i][j][0] = acc[i][j][1] = acc[i][j][2] = acc[i][j][3] = 0.f;

    {
        uint32_t b0 = sbase;
        CP16(b0 + sdst,                    gA_h);
        CP16(b0 + sdst + 16,               gA_h + 16);
        CP16(b0 + PROJ_TILE_B + sdst,      gA_l);
        CP16(b0 + PROJ_TILE_B + sdst + 16, gA_l + 16);
        CP16(b0 + 2 * PROJ_TILE_B + sdst,      gB_h);
        CP16(b0 + 2 * PROJ_TILE_B + sdst + 16, gB_h + 16);
        CP16(b0 + 3 * PROJ_TILE_B + sdst,      gB_l);
        CP16(b0 + 3 * PROJ_TILE_B + sdst + 16, gB_l + 16);
        CP_COMMIT();
    }

    for (int c = 0; c < 32; ++c) {
        const uint32_t bufb = sbase + (uint32_t)(c & 1) * PROJ_BUF_B;
        if (c + 1 < 32) {
            const uint32_t nb = sbase + (uint32_t)((c + 1) & 1) * PROJ_BUF_B;
            const int kb = (c + 1) * 64;
            CP16(nb + sdst,                    gA_h + kb);
            CP16(nb + sdst + 16,               gA_h + kb + 16);
            CP16(nb + PROJ_TILE_B + sdst,      gA_l + kb);
            CP16(nb + PROJ_TILE_B + sdst + 16, gA_l + kb + 16);
            CP16(nb + 2 * PROJ_TILE_B + sdst,      gB_h + kb);
            CP16(nb + 2 * PROJ_TILE_B + sdst + 16, gB_h + kb + 16);
            CP16(nb + 3 * PROJ_TILE_B + sdst,      gB_l + kb);
            CP16(nb + 3 * PROJ_TILE_B + sdst + 16, gB_l + kb + 16);
            CP_COMMIT();
            CP_WAIT1();
        } else {
            CP_WAIT0();
        }
        __syncthreads();

#pragma unroll
        for (int ks = 0; ks < 32; ks += 16) {
            const uint32_t ab = bufb + a_off + (uint32_t)(ks * 2);
            const uint32_t bb = bufb + 2 * PROJ_TILE_B + b_off + (uint32_t)(ks * 2);

            uint32_t ah[4][4], bhf[4][2], blf[4][2];
#pragma unroll
            for (int mt = 0; mt < 4; ++mt)
                LDSM_X4(ah[mt][0], ah[mt][1], ah[mt][2], ah[mt][3],
                        ab + (uint32_t)(mt * 1280));
#pragma unroll
            for (int nt = 0; nt < 4; ++nt)
                LDSM_X2(bhf[nt][0], bhf[nt][1], bb + (uint32_t)(nt * 640));
#pragma unroll
            for (int mt = 0; mt < 4; ++mt)
#pragma unroll
                for (int nt = 0; nt < 4; ++nt)
                    MMA_BF16(acc[mt][nt], ah[mt], bhf[nt]);
#pragma unroll
            for (int nt = 0; nt < 4; ++nt)
                LDSM_X2(blf[nt][0], blf[nt][1],
                        bb + (uint32_t)(PROJ_TILE_B + nt * 640));
#pragma unroll
            for (int mt = 0; mt < 4; ++mt)
#pragma unroll
                for (int nt = 0; nt < 4; ++nt)
                    MMA_BF16(acc[mt][nt], ah[mt], blf[nt]);
#pragma unroll
            for (int mt = 0; mt < 4; ++mt)
                LDSM_X4(ah[mt][0], ah[mt][1], ah[mt][2], ah[mt][3],
                        ab + (uint32_t)(PROJ_TILE_B + mt * 1280));
#pragma unroll
            for (int mt = 0; mt < 4; ++mt)
#pragma unroll
                for (int nt = 0; nt < 4; ++nt)
                    MMA_BF16(acc[mt][nt], ah[mt], bhf[nt]);
        }
        __syncthreads();
    }

    // Epilogue: bias + fp16 outputs
    const int g  = lane >> 2;
    const int t2 = (lane & 3) * 2;
    const float scale = (which == 0) ? 0.125f : 1.0f;
#pragma unroll
    for (int mt = 0; mt < 4; ++mt) {
        const int r0 = row0 + wm * 64 + mt * 16 + g;
        const int r1 = r0 + 8;
        const int bat = r0 >> 11;
        const int s0 = r0 & 2047, s1 = r1 & 2047;
#pragma unroll
        for (int nt = 0; nt < 4; ++nt) {
            const int col = col0 + wn * 32 + nt * 8 + t2;
            const float2 bv2 = *(const float2*)(bias + col);
            const int h = col >> 6, hd = col & 63;
            const int bh = bat * H_ + h;
            float v00 = (acc[mt][nt][0] + bv2.x) * scale;
            float v01 = (acc[mt][nt][1] + bv2.y) * scale;
            float v10 = (acc[mt][nt][2] + bv2.x) * scale;
            float v11 = (acc[mt][nt][3] + bv2.y) * scale;
            if (which == 0) {
                size_t o0 = ((size_t)bh * S_ + s0) * HD_ + hd;
                size_t o1 = ((size_t)bh * S_ + s1) * HD_ + hd;
                uint32_t h0 = packhf(v00, v01), h1 = packhf(v10, v11);
                float2 f0 = __half22float2(*(__half2*)&h0);
                float2 f1 = __half22float2(*(__half2*)&h1);
                *(uint32_t*)(g_qhi + o0) = h0;
                *(uint32_t*)(g_qhi + o1) = h1;
                *(uint32_t*)(g_qlo + o0) = packhf(v00 - f0.x, v01 - f0.y);
                *(uint32_t*)(g_qlo + o1) = packhf(v10 - f1.x, v11 - f1.y);
            } else if (which == 1) {
                size_t o0 = ((size_t)bh * S_ + s0) * HD_ + hd;
                size_t o1 = ((size_t)bh * S_ + s1) * HD_ + hd;
                *(uint32_t*)(g_kh + o0) = packhf(v00, v01);
                *(uint32_t*)(g_kh + o1) = packhf(v10, v11);
            } else {
                size_t base0 = ((size_t)bh * HD_ + hd) * S_;
                size_t base1 = base0 + S_;
                __half h00 = __float2half(v00), h01 = __float2half(v01);
                __half h10 = __float2half(v10), h11 = __float2half(v11);
                g_vthi[base0 + s0] = h00;
                g_vthi[base1 + s0] = h01;
                g_vthi[base0 + s1] = h10;
                g_vthi[base1 + s1] = h11;
                g_vtlo[base0 + s0] = __float2half(v00 - __half2float(h00));
                g_vtlo[base1 + s0] = __float2half(v01 - __half2float(h01));
                g_vtlo[base0 + s1] = __float2half(v10 - __half2float(h10));
                g_vtlo[base1 + s1] = __float2half(v11 - __half2float(h11));
            }
        }
    }
}

// ---------------------------------------------------------------------------
// fp16 HMMA flash attention. BR=64, BC=64, 4 warps (128 thr) -> 2 CTAs/SM.
// QK: (qhi+qlo) x Khi (4 n8-MMAs/step). PV: (Phi+Plo) x (Vhi+Vlo) minus lolo
// (6 n8-MMAs/step). Q in regs, P in regs, V pre-transposed.
// smem: 2 x {Khi 8K, Vhi 8K, Vlo 8K} + Qhi 8K + Qlo 8K = 64KB
// ---------------------------------------------------------------------------
#define ATTN_SMEM (65536 + 1024)

__global__ __launch_bounds__(128)
void attn_mma_kernel(float* __restrict__ out)
{
    extern __shared__ char asmem[];
    const uint32_t sb = (smem_u32(asmem) + 1023u) & ~1023u;

    const int tid  = threadIdx.x;
    const int lane = tid & 31, warp = tid >> 5;
    const int bh   = blockIdx.y;
    const int q0   = blockIdx.x * 64;

    const char* qh = (const char*)(g_qhi + (size_t)bh * S_ * HD_);
    const char* ql = (const char*)(g_qlo + (size_t)bh * S_ * HD_);
    const char* kh = (const char*)(g_kh  + (size_t)bh * S_ * HD_);
    const char* vh = (const char*)(g_vthi + (size_t)bh * HD_ * S_);
    const char* vl = (const char*)(g_vtlo + (size_t)bh * HD_ * S_);

    const int r8 = lane & 7;
    const int arow = ((lane >> 3) & 1) * 8 + r8;
    const int acol = lane >> 4;

    const int lrow  = tid >> 1;       // 0..63
    const int lhalf = tid & 1;        // 4-chunk halves

    // ---- stage Q tile [64][64] hi/lo ----
#pragma unroll
    for (int i = 0; i < 4; ++i) {
        int ch = lhalf * 4 + i;
        uint32_t off = SWZ(lrow * 128 + ch * 16);
        CP16(sb + 49152 + off, qh + (size_t)(q0 + lrow) * 128 + ch * 16);
        CP16(sb + 57344 + off, ql + (size_t)(q0 + lrow) * 128 + ch * 16);
    }
    CP_COMMIT();
    // ---- chunk 0 into buf0 ----
#pragma unroll
    for (int i = 0; i < 4; ++i) {
        int ch = lhalf * 4 + i;
        uint32_t off = SWZ(lrow * 128 + ch * 16);
        CP16(sb + off,         kh + (size_t)lrow * 128 + ch * 16);
        CP16(sb + 8192 + off,  vh + (size_t)lrow * (S_ * 2) + ch * 16);
        CP16(sb + 16384 + off, vl + (size_t)lrow * (S_ * 2) + ch * 16);
    }
    CP_COMMIT();
    CP_WAIT0();
    __syncthreads();

    // ---- Q fragments into registers ----
    uint32_t qa_h[4][4], qa_l[4][4];
#pragma unroll
    for (int ks = 0; ks < 4; ++ks) {
        int row = warp * 16 + arow;
        int ch  = ks * 2 + acol;
        uint32_t off = SWZ(row * 128 + ch * 16);
        LDSM_X4(qa_h[ks][0], qa_h[ks][1], qa_h[ks][2], qa_h[ks][3], sb + 49152 + off);
        LDSM_X4(qa_l[ks][0], qa_l[ks][1], qa_l[ks][2], qa_l[ks][3], sb + 57344 + off);
    }

    float m0 = -1e30f, m1 = -1e30f, l0 = 0.f, l1 = 0.f;
    float o[8][4];
#pragma unroll
    for (int nt = 0; nt < 8; ++nt)
        o[nt][0] = o[nt][1] = o[nt][2] = o[nt][3] = 0.f;

    for (int c = 0; c < 32; ++c) {
        if (c > 0) CP_WAIT0();
        __syncthreads();
        if (c + 1 < 32) {
            const uint32_t nb = sb + (uint32_t)((c + 1) & 1) * 24576;
            const int kb = (c + 1) * 64;
#pragma unroll
            for (int i = 0; i < 4; ++i) {
                int ch = lhalf * 4 + i;
                uint32_t off = SWZ(lrow * 128 + ch * 16);
                CP16(nb + off,         kh + (size_t)(kb + lrow) * 128 + ch * 16);
                CP16(nb + 8192 + off,  vh + (size_t)lrow * (S_ * 2) + kb * 2 + ch * 16);
                CP16(nb + 16384 + off, vl + (size_t)lrow * (S_ * 2) + kb * 2 + ch * 16);
            }
            CP_COMMIT();
        }
        const uint32_t buf = sb + (uint32_t)(c & 1) * 24576;

        // ---- S = Q @ Khi^T (2-term q split) ----
        float cc[8][4];
#pragma unroll
        for (int nt = 0; nt < 8; ++nt)
            cc[nt][0] = cc[nt][1] = cc[nt][2] = cc[nt][3] = 0.f;

#pragma unroll
        for (int ks = 0; ks < 4; ++ks) {
#pragma unroll
            for (int np = 0; np < 4; ++np) {
                int row = np * 16 + arow;
                int ch  = ks * 2 + acol;
                uint32_t off = SWZ(row * 128 + ch * 16);
                uint32_t b0, b1, b2, b3;
                LDSM_X4(b0, b1, b2, b3, buf + off);
                MMA_F16S(cc[2 * np],     qa_h[ks], b0, b2);
                MMA_F16S(cc[2 * np + 1], qa_h[ks], b1, b3);
                MMA_F16S(cc[2 * np],     qa_l[ks], b0, b2);
                MMA_F16S(cc[2 * np + 1], qa_l[ks], b1, b3);
            }
        }

        // ---- online softmax ----
        float rmx0 = cc[0][0], rmx1 = cc[0][2];
#pragma unroll
        for (int nt = 0; nt < 8; ++nt) {
            rmx0 = fmaxf(rmx0, fmaxf(cc[nt][0], cc[nt][1]));
            rmx1 = fmaxf(rmx1, fmaxf(cc[nt][2], cc[nt][3]));
        }
        rmx0 = fmaxf(rmx0, __shfl_xor_sync(0xffffffffu, rmx0, 1));
        rmx0 = fmaxf(rmx0, __shfl_xor_sync(0xffffffffu, rmx0, 2));
        rmx1 = fmaxf(rmx1, __shfl_xor_sync(0xffffffffu, rmx1, 1));
        rmx1 = fmaxf(rmx1, __shfl_xor_sync(0xffffffffu, rmx1, 2));
        float mn0 = fmaxf(m0, rmx0), mn1 = fmaxf(m1, rmx1);
        float cr0 = fexp(m0 - mn0), cr1 = fexp(m1 - mn1);
        m0 = mn0; m1 = mn1;
        float rs0 = 0.f, rs1 = 0.f;
#pragma unroll
        for (int nt = 0; nt < 8; ++nt) {
            cc[nt][0] = fexp(cc[nt][0] - mn0);
            cc[nt][1] = fexp(cc[nt][1] - mn0);
            cc[nt][2] = fexp(cc[nt][2] - mn1);
            cc[nt][3] = fexp(cc[nt][3] - mn1);
            rs0 += cc[nt][0] + cc[nt][1];
            rs1 += cc[nt][2] + cc[nt][3];
        }
        rs0 += __shfl_xor_sync(0xffffffffu, rs0, 1);
        rs0 += __shfl_xor_sync(0xffffffffu, rs0, 2);
        rs1 += __shfl_xor_sync(0xffffffffu, rs1, 1);
        rs1 += __shfl_xor_sync(0xffffffffu, rs1, 2);
        l0 = l0 * cr0 + rs0;
        l1 = l1 * cr1 + rs1;
#pragma unroll
        for (int nt = 0; nt < 8; ++nt) {
            o[nt][0] *= cr0; o[nt][1] *= cr0;
            o[nt][2] *= cr1; o[nt][3] *= cr1;
        }

        // ---- pack P into fp16 A fragments (hi/lo) ----
        uint32_t pa_h[4][4], pa_l[4][4];
#pragma unroll
        for (int j = 0; j < 4; ++j) {
            float x0 = cc[2 * j][0],     x1 = cc[2 * j][1];
            float x2 = cc[2 * j][2],     x3 = cc[2 * j][3];
            float x4 = cc[2 * j + 1][0], x5 = cc[2 * j + 1][1];
            float x6 = cc[2 * j + 1][2], x7 = cc[2 * j + 1][3];
            uint32_t h0 = packhf(x0, x1), h1 = packhf(x2, x3);
            uint32_t h2 = packhf(x4, x5), h3 = packhf(x6, x7);
            pa_h[j][0] = h0; pa_h[j][1] = h1; pa_h[j][2] = h2; pa_h[j][3] = h3;
            float2 f0 = __half22float2(*(__half2*)&h0);
            float2 f1 = __half22float2(*(__half2*)&h1);
            float2 f2 = __half22float2(*(__half2*)&h2);
            float2 f3 = __half22float2(*(__half2*)&h3);
            pa_l[j][0] = packhf(x0 - f0.x, x1 - f0.y);
            pa_l[j][1] = packhf(x2 - f1.x, x3 - f1.y);
            pa_l[j][2] = packhf(x4 - f2.x, x5 - f2.y);
            pa_l[j][3] = packhf(x6 - f3.x, x7 - f3.y);
        }

        // ---- O += P @ V (3-term split) ----
#pragma unroll
        for (int j = 0; j < 4; ++j) {
#pragma unroll
            for (int np = 0; np < 4; ++np) {
                int row = np * 16 + arow;
                int ch  = j * 2 + acol;
                uint32_t off = SWZ(row * 128 + ch * 16);
                uint32_t b0, b1, b2, b3;
                LDSM_X4(b0, b1, b2, b3, buf + 8192 + off);     // V hi
                MMA_F16S(o[2 * np],     pa_h[j], b0, b2);
                MMA_F16S(o[2 * np + 1], pa_h[j], b1, b3);
                MMA_F16S(o[2 * np],     pa_l[j], b0, b2);
                MMA_F16S(o[2 * np + 1], pa_l[j], b1, b3);
                LDSM_X4(b0, b1, b2, b3, buf + 16384 + off);    // V lo
                MMA_F16S(o[2 * np],     pa_h[j], b0, b2);
                MMA_F16S(o[2 * np + 1], pa_h[j], b1, b3);
            }
        }
    }

    // ---- epilogue ----
    const int g  = lane >> 2;
    const int t2 = (lane & 3) * 2;
    const int bat = bh >> 4, h = bh & 15;
    const int s0 = q0 + warp * 16 + g, s1 = s0 + 8;
    const float inv0 = 1.0f / l0, inv1 = 1.0f / l1;
#pragma unroll
    for (int nt = 0; nt < 8; ++nt) {
        int col = h * HD_ + nt * 8 + t2;
        float2 v0, v1;
        v0.x = o[nt][0] * inv0; v0.y = o[nt][1] * inv0;
        v1.x = o[nt][2] * inv1; v1.y = o[nt][3] * inv1;
        *(float2*)(out + ((size_t)bat * S_ + s0) * DM + col) = v0;
        *(float2*)(out + ((size_t)bat * S_ + s1) * DM + col) = v1;
    }
}

// ---------------------------------------------------------------------------
extern "C" void kernel_launch(void* const* d_in, const int* in_sizes, int n_in,
                              void* d_out, int out_size)
{
    (void)in_sizes; (void)n_in; (void)out_size;
    const float* Q  = (const float*)d_in[0];
    const float* V  = (const float*)d_in[1];
    const float* K  = (const float*)d_in[2];
    const float* wq = (const float*)d_in[3];
    const float* bq = (const float*)d_in[4];
    const float* wk = (const float*)d_in[5];
    const float* bk = (const float*)d_in[6];
    const float* wv = (const float*)d_in[7];
    const float* bv = (const float*)d_in[8];
    float* out = (float*)d_out;

    dim3 xg((MX * DIN) / 4 / 256, 3);
    conv_x_kernel<<<xg, 256>>>(Q, K, V);
    dim3 wg(DM / 32, DIN / 32, 3);
    conv_w_kernel<<<wg, 256>>>(wq, wk, wv);

    cudaFuncSetAttribute(proj_mma_kernel, cudaFuncAttributeMaxDynamicSharedMemorySize, PROJ_SMEM);
    dim3 pg(DM / 128, MX / 128, 3);
    proj_mma_kernel<<<pg, 256, PROJ_SMEM>>>(bq, bk, bv);

    cudaFuncSetAttribute(attn_mma_kernel, cudaFuncAttributeMaxDynamicSharedMemorySize, ATTN_SMEM);
    dim3 ag(S_ / 64, B_ * H_);
    attn_mma_kernel<<<ag, 128, ATTN_SMEM>>>(out);
}